// round 4
// baseline (speedup 1.0000x reference)
#include <cuda_runtime.h>
#include <cstdint>

// ---------------- problem constants (fixed by reference setup) ----------------
#define N_SRC0 100000
#define N_DST0 20000
#define N_DST1 4000
#define NEDGE0 500000
#define NEDGE1 100000
#define D_IN 128
#define D_H 256

// ---------------- scratch (device globals; no allocation allowed) -------------
__device__ float g_acc0[N_DST0 * D_IN];   // layer0 segment sums
__device__ float g_cnt0[N_DST0];          // layer0 counts -> reciprocals
__device__ float g_h[N_DST0 * D_H];       // layer0 output (relu'd)
__device__ float g_acc1[N_DST1 * D_H];    // layer1 segment sums
__device__ float g_cnt1[N_DST1];          // layer1 counts -> reciprocals
__device__ float g_out[N_DST1 * D_H];     // layer1 raw output (pre-softmax)

// ---------------- zero scratch ----------------
__global__ void zero_kernel() {
    int tid = blockIdx.x * blockDim.x + threadIdx.x;
    int stride = gridDim.x * blockDim.x;
    for (int i = tid; i < N_DST0 * D_IN; i += stride) g_acc0[i] = 0.f;
    for (int i = tid; i < N_DST0; i += stride)        g_cnt0[i] = 0.f;
    for (int i = tid; i < N_DST1 * D_H; i += stride)  g_acc1[i] = 0.f;
    for (int i = tid; i < N_DST1; i += stride)        g_cnt1[i] = 0.f;
}

// ---------------- edge scatter, layer 0: one warp per edge (128 floats) -------
// edge_index is int32 (JAX x64 disabled: astype(int64) is a silent no-op).
__global__ void scatter0_kernel(const int* __restrict__ ei,
                                const float* __restrict__ x) {
    int gt = blockIdx.x * blockDim.x + threadIdx.x;
    int e = gt >> 5;
    int lane = gt & 31;
    if (e >= NEDGE0) return;
    int s = ei[e];
    int d = ei[NEDGE0 + e];
    float4 v = ((const float4*)(x + (size_t)s * D_IN))[lane];  // 32 lanes * 4 = 128
    float* dst = g_acc0 + (size_t)d * D_IN + lane * 4;
    asm volatile("red.global.add.v4.f32 [%0], {%1,%2,%3,%4};"
                 :: "l"(dst), "f"(v.x), "f"(v.y), "f"(v.z), "f"(v.w) : "memory");
    if (lane == 0) atomicAdd(&g_cnt0[d], 1.f);
}

// ---------------- edge scatter, layer 1: one warp per edge (256 floats) -------
__global__ void scatter1_kernel(const int* __restrict__ ei) {
    int gt = blockIdx.x * blockDim.x + threadIdx.x;
    int e = gt >> 5;
    int lane = gt & 31;
    if (e >= NEDGE1) return;
    int s = ei[e];
    int d = ei[NEDGE1 + e];
    const float4* hs = (const float4*)(g_h + (size_t)s * D_H);
    float4 v0 = hs[lane];
    float4 v1 = hs[lane + 32];
    float* dst0 = g_acc1 + (size_t)d * D_H + lane * 4;
    float* dst1 = dst0 + 128;
    asm volatile("red.global.add.v4.f32 [%0], {%1,%2,%3,%4};"
                 :: "l"(dst0), "f"(v0.x), "f"(v0.y), "f"(v0.z), "f"(v0.w) : "memory");
    asm volatile("red.global.add.v4.f32 [%0], {%1,%2,%3,%4};"
                 :: "l"(dst1), "f"(v1.x), "f"(v1.y), "f"(v1.z), "f"(v1.w) : "memory");
    if (lane == 0) atomicAdd(&g_cnt1[d], 1.f);
}

// ---------------- counts -> reciprocals (1/max(cnt,1)) ------------------------
// Must run AFTER the corresponding scatter (cnt1 was previously being inverted
// before scatter1 filled it -- that was the R2 correctness bug).
__global__ void invcnt0_kernel() {
    int i = blockIdx.x * blockDim.x + threadIdx.x;
    if (i < N_DST0) g_cnt0[i] = 1.f / fmaxf(g_cnt0[i], 1.f);
}
__global__ void invcnt1_kernel() {
    int i = blockIdx.x * blockDim.x + threadIdx.x;
    if (i < N_DST1) g_cnt1[i] = 1.f / fmaxf(g_cnt1[i], 1.f);
}

// ---------------- dual-A GEMM: out = scale(A1)@W1 + A2@W2 + b  (opt relu) -----
// A1: [M,K] segment sums, scaled per-row by inv[m] during load.
// A2: [M,K] dst features. W1,W2: [K,256] row-major. out: [M,256].
#define BM 64
#define BN 64
#define BK 16
__global__ void __launch_bounds__(256)
gemm_dual_kernel(const float* __restrict__ A1, const float* __restrict__ inv,
                 const float* __restrict__ A2,
                 const float* __restrict__ W1, const float* __restrict__ W2,
                 const float* __restrict__ bias,
                 float* __restrict__ out, int M, int K, int do_relu) {
    __shared__ float As[BM][BK];
    __shared__ float Bs[BK][BN + 1];

    int bm = blockIdx.y * BM;
    int bn = blockIdx.x * BN;
    int tx = threadIdx.x & 15;   // 0..15 -> 4 cols each
    int ty = threadIdx.x >> 4;   // 0..15 -> 4 rows each

    float acc[4][4];
#pragma unroll
    for (int i = 0; i < 4; i++)
#pragma unroll
        for (int j = 0; j < 4; j++) acc[i][j] = 0.f;

    for (int pass = 0; pass < 2; pass++) {
        const float* A = pass ? A2 : A1;
        const float* W = pass ? W2 : W1;
        for (int k0 = 0; k0 < K; k0 += BK) {
            // load A tile (BM x BK), apply per-row mean scale on pass 0
            for (int i = threadIdx.x; i < BM * BK; i += 256) {
                int r = i / BK, c = i % BK;
                int gr = bm + r;
                float v = 0.f;
                if (gr < M) {
                    v = A[(size_t)gr * K + k0 + c];
                    if (pass == 0) v *= inv[gr];
                }
                As[r][c] = v;
            }
            // load W tile (BK x BN); N stride is always 256
            for (int i = threadIdx.x; i < BK * BN; i += 256) {
                int r = i / BN, c = i % BN;
                Bs[r][c] = W[(size_t)(k0 + r) * D_H + bn + c];
            }
            __syncthreads();
#pragma unroll
            for (int k = 0; k < BK; k++) {
                float a[4], b[4];
#pragma unroll
                for (int i = 0; i < 4; i++) a[i] = As[ty * 4 + i][k];
#pragma unroll
                for (int j = 0; j < 4; j++) b[j] = Bs[k][tx * 4 + j];
#pragma unroll
                for (int i = 0; i < 4; i++)
#pragma unroll
                    for (int j = 0; j < 4; j++) acc[i][j] = fmaf(a[i], b[j], acc[i][j]);
            }
            __syncthreads();
        }
    }

#pragma unroll
    for (int i = 0; i < 4; i++) {
        int gm = bm + ty * 4 + i;
        if (gm >= M) continue;
#pragma unroll
        for (int j = 0; j < 4; j++) {
            int gn = bn + tx * 4 + j;
            float v = acc[i][j] + bias[gn];
            if (do_relu) v = fmaxf(v, 0.f);
            out[(size_t)gm * D_H + gn] = v;
        }
    }
}

// ---------------- epilogue: copy raw out + log_softmax ------------------------
__global__ void emit_kernel(const float* __restrict__ in,
                            float* __restrict__ out_raw,
                            float* __restrict__ out_ls) {
    int row = blockIdx.x;
    int t = threadIdx.x;
    float v = in[row * D_H + t];
    __shared__ float red[D_H];
    red[t] = v;
    __syncthreads();
#pragma unroll
    for (int s = 128; s > 0; s >>= 1) {
        if (t < s) red[t] = fmaxf(red[t], red[t + s]);
        __syncthreads();
    }
    float m = red[0];
    __syncthreads();
    float e = expf(v - m);
    red[t] = e;
    __syncthreads();
#pragma unroll
    for (int s = 128; s > 0; s >>= 1) {
        if (t < s) red[t] += red[t + s];
        __syncthreads();
    }
    float ls = v - m - logf(red[0]);
    if (out_raw) out_raw[row * D_H + t] = v;
    out_ls[row * D_H + t] = ls;
}

// ---------------- launch ------------------------------------------------------
extern "C" void kernel_launch(void* const* d_in, const int* in_sizes, int n_in,
                              void* d_out, int out_size) {
    const float* x     = (const float*)d_in[0];
    const int* ei0     = (const int*)d_in[1];
    const int* ei1     = (const int*)d_in[2];
    const float* W_l0  = (const float*)d_in[3];
    const float* b_l0  = (const float*)d_in[4];
    const float* W_r0  = (const float*)d_in[5];
    const float* W_l1  = (const float*)d_in[6];
    const float* b_l1  = (const float*)d_in[7];
    const float* W_r1  = (const float*)d_in[8];
    float* out         = (float*)d_out;

    float *p_acc0, *p_cnt0, *p_h, *p_acc1, *p_cnt1, *p_out;
    cudaGetSymbolAddress((void**)&p_acc0, g_acc0);
    cudaGetSymbolAddress((void**)&p_cnt0, g_cnt0);
    cudaGetSymbolAddress((void**)&p_h,    g_h);
    cudaGetSymbolAddress((void**)&p_acc1, g_acc1);
    cudaGetSymbolAddress((void**)&p_cnt1, g_cnt1);
    cudaGetSymbolAddress((void**)&p_out,  g_out);

    zero_kernel<<<512, 256>>>();

    scatter0_kernel<<<(NEDGE0 * 32 + 255) / 256, 256>>>(ei0, x);
    invcnt0_kernel<<<(N_DST0 + 255) / 256, 256>>>();

    // layer 0: h = relu(mean0 @ W_l0 + b_l0 + x[:20000] @ W_r0)
    gemm_dual_kernel<<<dim3(D_H / BN, (N_DST0 + BM - 1) / BM), 256>>>(
        p_acc0, p_cnt0, x, W_l0, W_r0, b_l0, p_h, N_DST0, D_IN, 1);

    scatter1_kernel<<<(NEDGE1 * 32 + 255) / 256, 256>>>(ei1);
    invcnt1_kernel<<<(N_DST1 + 255) / 256, 256>>>();

    // layer 1: out = mean1 @ W_l1 + b_l1 + h[:4000] @ W_r1
    gemm_dual_kernel<<<dim3(D_H / BN, (N_DST1 + BM - 1) / BM), 256>>>(
        p_acc1, p_cnt1, p_h, W_l1, W_r1, b_l1, p_out, N_DST1, D_H, 0);

    // emit: reference returns (out, log_softmax(out)) -> concatenated if room
    const int NM = N_DST1 * D_H;
    float* out_raw = (out_size >= 2 * NM) ? out : nullptr;
    float* out_ls  = (out_size >= 2 * NM) ? out + NM : out;
    emit_kernel<<<N_DST1, D_H>>>(p_out, out_raw, out_ls);
}

// round 5
// speedup vs baseline: 1.2334x; 1.2334x over previous
#include <cuda_runtime.h>
#include <cstdint>

// ---------------- problem constants (fixed by reference setup) ----------------
#define N_SRC0 100000
#define N_DST0 20000
#define N_DST1 4000
#define NEDGE0 500000
#define NEDGE1 100000
#define D_IN 128
#define D_H 256

// ---------------- scratch (device globals; no allocation allowed) -------------
__device__ float g_acc0[N_DST0 * D_IN];   // layer0 segment sums
__device__ float g_cnt0[N_DST0];          // layer0 counts -> reciprocals
__device__ float g_h[N_DST0 * D_H];       // layer0 output (relu'd)
__device__ float g_acc1[N_DST1 * D_H];    // layer1 segment sums
__device__ float g_cnt1[N_DST1];          // layer1 counts -> reciprocals
__device__ float g_out[N_DST1 * D_H];     // layer1 raw output (pre-softmax)

// ---------------- zero scratch (float4) ----------------
__global__ void zero_kernel() {
    int tid = blockIdx.x * blockDim.x + threadIdx.x;
    int stride = gridDim.x * blockDim.x;
    float4 z = make_float4(0.f, 0.f, 0.f, 0.f);
    float4* a0 = (float4*)g_acc0;
    float4* a1 = (float4*)g_acc1;
    for (int i = tid; i < N_DST0 * D_IN / 4; i += stride) a0[i] = z;
    for (int i = tid; i < N_DST1 * D_H / 4; i += stride)  a1[i] = z;
    for (int i = tid; i < N_DST0; i += stride)            g_cnt0[i] = 0.f;
    for (int i = tid; i < N_DST1; i += stride)            g_cnt1[i] = 0.f;
}

// ---------------- edge scatter, layer 0: one warp per edge (128 floats) -------
// edge_index is int32 (JAX x64 disabled: astype(int64) is a silent no-op).
__global__ void scatter0_kernel(const int* __restrict__ ei,
                                const float* __restrict__ x) {
    int gt = blockIdx.x * blockDim.x + threadIdx.x;
    int e = gt >> 5;
    int lane = gt & 31;
    if (e >= NEDGE0) return;
    int s = ei[e];
    int d = ei[NEDGE0 + e];
    float4 v = ((const float4*)(x + (size_t)s * D_IN))[lane];  // 32 lanes * 4 = 128
    float* dst = g_acc0 + (size_t)d * D_IN + lane * 4;
    asm volatile("red.global.add.v4.f32 [%0], {%1,%2,%3,%4};"
                 :: "l"(dst), "f"(v.x), "f"(v.y), "f"(v.z), "f"(v.w) : "memory");
    if (lane == 0) atomicAdd(&g_cnt0[d], 1.f);
}

// ---------------- edge scatter, layer 1: one warp per edge (256 floats) -------
__global__ void scatter1_kernel(const int* __restrict__ ei) {
    int gt = blockIdx.x * blockDim.x + threadIdx.x;
    int e = gt >> 5;
    int lane = gt & 31;
    if (e >= NEDGE1) return;
    int s = ei[e];
    int d = ei[NEDGE1 + e];
    const float4* hs = (const float4*)(g_h + (size_t)s * D_H);
    float4 v0 = hs[lane];
    float4 v1 = hs[lane + 32];
    float* dst0 = g_acc1 + (size_t)d * D_H + lane * 4;
    float* dst1 = dst0 + 128;
    asm volatile("red.global.add.v4.f32 [%0], {%1,%2,%3,%4};"
                 :: "l"(dst0), "f"(v0.x), "f"(v0.y), "f"(v0.z), "f"(v0.w) : "memory");
    asm volatile("red.global.add.v4.f32 [%0], {%1,%2,%3,%4};"
                 :: "l"(dst1), "f"(v1.x), "f"(v1.y), "f"(v1.z), "f"(v1.w) : "memory");
    if (lane == 0) atomicAdd(&g_cnt1[d], 1.f);
}

// ---------------- counts -> reciprocals (1/max(cnt,1)), after each scatter ----
__global__ void invcnt0_kernel() {
    int i = blockIdx.x * blockDim.x + threadIdx.x;
    if (i < N_DST0) g_cnt0[i] = 1.f / fmaxf(g_cnt0[i], 1.f);
}
__global__ void invcnt1_kernel() {
    int i = blockIdx.x * blockDim.x + threadIdx.x;
    if (i < N_DST1) g_cnt1[i] = 1.f / fmaxf(g_cnt1[i], 1.f);
}

// ---------------- dual-A GEMM: out = scale(A1)@W1 + A2@W2 + b  (opt relu) -----
// 128x128x8 tile, 256 threads, 8x8 microtile, As transposed for float4 LDS.
#define BM 128
#define BN 128
#define BK 8
__global__ void __launch_bounds__(256, 2)
gemm_dual_kernel(const float* __restrict__ A1, const float* __restrict__ inv,
                 const float* __restrict__ A2,
                 const float* __restrict__ W1, const float* __restrict__ W2,
                 const float* __restrict__ bias,
                 float* __restrict__ out, int M, int K, int do_relu) {
    __shared__ float As[BK][BM];     // transposed A tile
    __shared__ float Bs[BK][BN];

    const int tid = threadIdx.x;
    const int tx = tid & 15;         // 0..15 -> 8 cols each
    const int ty = tid >> 4;         // 0..15 -> 8 rows each
    const int bm = blockIdx.y * BM;
    const int bn = blockIdx.x * BN;

    // A tile load mapping: 128 rows x 8 k -> one float4 per thread
    const int a_row = tid >> 1;            // 0..127
    const int a_kc  = (tid & 1) * 4;       // 0 or 4
    // B tile load mapping: 8 k-rows x 128 cols -> one float4 per thread
    const int b_kr  = tid >> 5;            // 0..7
    const int b_col = (tid & 31) * 4;      // 0..124

    float acc[8][8];
#pragma unroll
    for (int i = 0; i < 8; i++)
#pragma unroll
        for (int j = 0; j < 8; j++) acc[i][j] = 0.f;

    for (int pass = 0; pass < 2; pass++) {
        const float* __restrict__ A = pass ? A2 : A1;
        const float* __restrict__ W = pass ? W2 : W1;
        const int gr = bm + a_row;
        float rscale = 1.f;
        if (pass == 0 && gr < M) rscale = inv[gr];

        for (int k0 = 0; k0 < K; k0 += BK) {
            float4 av = make_float4(0.f, 0.f, 0.f, 0.f);
            if (gr < M) {
                av = *(const float4*)&A[(size_t)gr * K + k0 + a_kc];
                if (pass == 0) { av.x *= rscale; av.y *= rscale; av.z *= rscale; av.w *= rscale; }
            }
            float4 bv = *(const float4*)&W[(size_t)(k0 + b_kr) * D_H + bn + b_col];
            __syncthreads();   // protect previous iteration's reads
            As[a_kc + 0][a_row] = av.x;
            As[a_kc + 1][a_row] = av.y;
            As[a_kc + 2][a_row] = av.z;
            As[a_kc + 3][a_row] = av.w;
            *(float4*)&Bs[b_kr][b_col] = bv;
            __syncthreads();
#pragma unroll
            for (int k = 0; k < BK; k++) {
                float4 a0 = *(const float4*)&As[k][ty * 8];
                float4 a1 = *(const float4*)&As[k][ty * 8 + 4];
                float4 b0 = *(const float4*)&Bs[k][tx * 8];
                float4 b1 = *(const float4*)&Bs[k][tx * 8 + 4];
                float a[8] = {a0.x, a0.y, a0.z, a0.w, a1.x, a1.y, a1.z, a1.w};
                float b[8] = {b0.x, b0.y, b0.z, b0.w, b1.x, b1.y, b1.z, b1.w};
#pragma unroll
                for (int i = 0; i < 8; i++)
#pragma unroll
                    for (int j = 0; j < 8; j++)
                        acc[i][j] = fmaf(a[i], b[j], acc[i][j]);
            }
        }
    }

    // epilogue: add bias, optional relu, float4 stores
    const int gn = bn + tx * 8;
    float bb[8];
#pragma unroll
    for (int j = 0; j < 8; j++) bb[j] = bias[gn + j];
#pragma unroll
    for (int i = 0; i < 8; i++) {
        int gm = bm + ty * 8 + i;
        if (gm >= M) continue;
        float4 o0, o1;
        o0.x = acc[i][0] + bb[0]; o0.y = acc[i][1] + bb[1];
        o0.z = acc[i][2] + bb[2]; o0.w = acc[i][3] + bb[3];
        o1.x = acc[i][4] + bb[4]; o1.y = acc[i][5] + bb[5];
        o1.z = acc[i][6] + bb[6]; o1.w = acc[i][7] + bb[7];
        if (do_relu) {
            o0.x = fmaxf(o0.x, 0.f); o0.y = fmaxf(o0.y, 0.f);
            o0.z = fmaxf(o0.z, 0.f); o0.w = fmaxf(o0.w, 0.f);
            o1.x = fmaxf(o1.x, 0.f); o1.y = fmaxf(o1.y, 0.f);
            o1.z = fmaxf(o1.z, 0.f); o1.w = fmaxf(o1.w, 0.f);
        }
        float* op = out + (size_t)gm * D_H + gn;
        *(float4*)op = o0;
        *(float4*)(op + 4) = o1;
    }
}

// ---------------- epilogue: copy raw out + log_softmax ------------------------
__global__ void emit_kernel(const float* __restrict__ in,
                            float* __restrict__ out_raw,
                            float* __restrict__ out_ls) {
    int row = blockIdx.x;
    int t = threadIdx.x;
    float v = in[row * D_H + t];
    __shared__ float red[D_H];
    red[t] = v;
    __syncthreads();
#pragma unroll
    for (int s = 128; s > 0; s >>= 1) {
        if (t < s) red[t] = fmaxf(red[t], red[t + s]);
        __syncthreads();
    }
    float m = red[0];
    __syncthreads();
    float e = expf(v - m);
    red[t] = e;
    __syncthreads();
#pragma unroll
    for (int s = 128; s > 0; s >>= 1) {
        if (t < s) red[t] += red[t + s];
        __syncthreads();
    }
    float ls = v - m - logf(red[0]);
    if (out_raw) out_raw[row * D_H + t] = v;
    out_ls[row * D_H + t] = ls;
}

// ---------------- launch ------------------------------------------------------
extern "C" void kernel_launch(void* const* d_in, const int* in_sizes, int n_in,
                              void* d_out, int out_size) {
    const float* x     = (const float*)d_in[0];
    const int* ei0     = (const int*)d_in[1];
    const int* ei1     = (const int*)d_in[2];
    const float* W_l0  = (const float*)d_in[3];
    const float* b_l0  = (const float*)d_in[4];
    const float* W_r0  = (const float*)d_in[5];
    const float* W_l1  = (const float*)d_in[6];
    const float* b_l1  = (const float*)d_in[7];
    const float* W_r1  = (const float*)d_in[8];
    float* out         = (float*)d_out;

    float *p_acc0, *p_cnt0, *p_h, *p_acc1, *p_cnt1, *p_out;
    cudaGetSymbolAddress((void**)&p_acc0, g_acc0);
    cudaGetSymbolAddress((void**)&p_cnt0, g_cnt0);
    cudaGetSymbolAddress((void**)&p_h,    g_h);
    cudaGetSymbolAddress((void**)&p_acc1, g_acc1);
    cudaGetSymbolAddress((void**)&p_cnt1, g_cnt1);
    cudaGetSymbolAddress((void**)&p_out,  g_out);

    zero_kernel<<<592, 256>>>();

    scatter0_kernel<<<(NEDGE0 * 32 + 255) / 256, 256>>>(ei0, x);
    invcnt0_kernel<<<(N_DST0 + 255) / 256, 256>>>();

    // layer 0: h = relu(mean0 @ W_l0 + b_l0 + x[:20000] @ W_r0)
    gemm_dual_kernel<<<dim3(D_H / BN, (N_DST0 + BM - 1) / BM), 256>>>(
        p_acc0, p_cnt0, x, W_l0, W_r0, b_l0, p_h, N_DST0, D_IN, 1);

    scatter1_kernel<<<(NEDGE1 * 32 + 255) / 256, 256>>>(ei1);
    invcnt1_kernel<<<(N_DST1 + 255) / 256, 256>>>();

    // layer 1: out = mean1 @ W_l1 + b_l1 + h[:4000] @ W_r1
    gemm_dual_kernel<<<dim3(D_H / BN, (N_DST1 + BM - 1) / BM), 256>>>(
        p_acc1, p_cnt1, p_h, W_l1, W_r1, b_l1, p_out, N_DST1, D_H, 0);

    // emit: reference returns (out, log_softmax(out)) -> concatenated if room
    const int NM = N_DST1 * D_H;
    float* out_raw = (out_size >= 2 * NM) ? out : nullptr;
    float* out_ls  = (out_size >= 2 * NM) ? out + NM : out;
    emit_kernel<<<N_DST1, D_H>>>(p_out, out_raw, out_ls);
}